// round 1
// baseline (speedup 1.0000x reference)
#include <cuda_runtime.h>
#include <cstdint>

// Problem constants
#define Bc 4
#define Tc 4096
#define Cc 1024
#define MT (Bc * Tc)   // 16384 total rows

// GEMM tiling
#define BM 128
#define BN 128
#define BK 16
#define TM 8
#define TN 8
#define NTHREADS 256

#define NEG_INF __int_as_float(0xff800000)

// Scratch (device globals: allocation rules forbid cudaMalloc)
__device__ float g_Q[(size_t)MT * Cc];          // 64 MB
__device__ float g_K[(size_t)MT * Cc];          // 64 MB
__device__ float g_V[(size_t)MT * Cc];          // 64 MB
__device__ float g_S[(size_t)Bc * Tc * Tc];     // 256 MB (scores -> probs in-place)
__device__ float g_AO[(size_t)MT * Cc];         // 64 MB (attention output)

// ---------------------------------------------------------------------------
// Shared GEMM inner bodies.
//   gemm_bt_acc: C[M,N] += A[M,K] * B[N,K]^T   (both operands K-major)
//   gemm_nn_acc: C[M,N] += A[M,K] * B[K,N]     (B N-major), K loop bounded by kmax
// Tile: 128x128x16, 256 threads, 8x8 per-thread microtile, fp32.
// ---------------------------------------------------------------------------

__device__ __forceinline__ void gemm_bt_acc(
    const float* __restrict__ A, const float* __restrict__ B,
    int K, int m0, int n0,
    float (&acc)[TM][TN],
    float (*As)[BM], float (*Bs)[BN])
{
    const int tid  = threadIdx.x;
    const int tx   = tid & 15;
    const int ty   = tid >> 4;
    const int lrow = tid >> 2;          // 0..63
    const int lc4  = (tid & 3) << 2;    // 0,4,8,12

    const float* Ap  = A + (size_t)(m0 + lrow) * K + lc4;
    const float* Ap2 = Ap + (size_t)64 * K;
    const float* Bp  = B + (size_t)(n0 + lrow) * K + lc4;
    const float* Bp2 = Bp + (size_t)64 * K;

    for (int kt = 0; kt < K; kt += BK) {
        float4 a0 = *(const float4*)(Ap  + kt);
        float4 a1 = *(const float4*)(Ap2 + kt);
        float4 b0 = *(const float4*)(Bp  + kt);
        float4 b1 = *(const float4*)(Bp2 + kt);

        As[lc4 + 0][lrow]      = a0.x; As[lc4 + 1][lrow]      = a0.y;
        As[lc4 + 2][lrow]      = a0.z; As[lc4 + 3][lrow]      = a0.w;
        As[lc4 + 0][lrow + 64] = a1.x; As[lc4 + 1][lrow + 64] = a1.y;
        As[lc4 + 2][lrow + 64] = a1.z; As[lc4 + 3][lrow + 64] = a1.w;

        Bs[lc4 + 0][lrow]      = b0.x; Bs[lc4 + 1][lrow]      = b0.y;
        Bs[lc4 + 2][lrow]      = b0.z; Bs[lc4 + 3][lrow]      = b0.w;
        Bs[lc4 + 0][lrow + 64] = b1.x; Bs[lc4 + 1][lrow + 64] = b1.y;
        Bs[lc4 + 2][lrow + 64] = b1.z; Bs[lc4 + 3][lrow + 64] = b1.w;

        __syncthreads();

        #pragma unroll
        for (int kk = 0; kk < BK; ++kk) {
            float af[TM], bf[TN];
            #pragma unroll
            for (int i = 0; i < TM; ++i) af[i] = As[kk][ty * TM + i];
            #pragma unroll
            for (int j = 0; j < TN; ++j) bf[j] = Bs[kk][tx * TN + j];
            #pragma unroll
            for (int i = 0; i < TM; ++i)
                #pragma unroll
                for (int j = 0; j < TN; ++j)
                    acc[i][j] = fmaf(af[i], bf[j], acc[i][j]);
        }
        __syncthreads();
    }
}

__device__ __forceinline__ void gemm_nn_acc(
    const float* __restrict__ A, const float* __restrict__ B,
    int K, int N, int m0, int n0, int kmax,
    float (&acc)[TM][TN],
    float (*As)[BM], float (*Bs)[BN])
{
    const int tid  = threadIdx.x;
    const int tx   = tid & 15;
    const int ty   = tid >> 4;
    const int lrow = tid >> 2;          // 0..63
    const int lc4  = (tid & 3) << 2;
    const int krow = tid >> 4;          // 0..15
    const int nc4  = (tid & 15) << 2;   // 0..60

    const float* Ap  = A + (size_t)(m0 + lrow) * K + lc4;
    const float* Ap2 = Ap + (size_t)64 * K;

    for (int kt = 0; kt < kmax; kt += BK) {
        float4 a0 = *(const float4*)(Ap  + kt);
        float4 a1 = *(const float4*)(Ap2 + kt);
        const float* bp = B + (size_t)(kt + krow) * N + n0 + nc4;
        float4 b0 = *(const float4*)(bp);
        float4 b1 = *(const float4*)(bp + 64);

        As[lc4 + 0][lrow]      = a0.x; As[lc4 + 1][lrow]      = a0.y;
        As[lc4 + 2][lrow]      = a0.z; As[lc4 + 3][lrow]      = a0.w;
        As[lc4 + 0][lrow + 64] = a1.x; As[lc4 + 1][lrow + 64] = a1.y;
        As[lc4 + 2][lrow + 64] = a1.z; As[lc4 + 3][lrow + 64] = a1.w;

        *(float4*)&Bs[krow][nc4]      = b0;
        *(float4*)&Bs[krow][nc4 + 64] = b1;

        __syncthreads();

        #pragma unroll
        for (int kk = 0; kk < BK; ++kk) {
            float af[TM], bf[TN];
            #pragma unroll
            for (int i = 0; i < TM; ++i) af[i] = As[kk][ty * TM + i];
            #pragma unroll
            for (int j = 0; j < TN; ++j) bf[j] = Bs[kk][tx * TN + j];
            #pragma unroll
            for (int i = 0; i < TM; ++i)
                #pragma unroll
                for (int j = 0; j < TN; ++j)
                    acc[i][j] = fmaf(af[i], bf[j], acc[i][j]);
        }
        __syncthreads();
    }
}

__device__ __forceinline__ void store_tile(
    float* __restrict__ C, int ldc, int m0, int n0,
    float (&acc)[TM][TN], const float* __restrict__ bias)
{
    const int tx = threadIdx.x & 15;
    const int ty = threadIdx.x >> 4;
    float b[TN];
    if (bias) {
        #pragma unroll
        for (int j = 0; j < TN; ++j) b[j] = bias[n0 + tx * TN + j];
    } else {
        #pragma unroll
        for (int j = 0; j < TN; ++j) b[j] = 0.0f;
    }
    #pragma unroll
    for (int i = 0; i < TM; ++i) {
        int r = m0 + ty * TM + i;
        float* cp = C + (size_t)r * ldc + n0 + tx * TN;
        *(float4*)(cp)     = make_float4(acc[i][0] + b[0], acc[i][1] + b[1],
                                         acc[i][2] + b[2], acc[i][3] + b[3]);
        *(float4*)(cp + 4) = make_float4(acc[i][4] + b[4], acc[i][5] + b[5],
                                         acc[i][6] + b[6], acc[i][7] + b[7]);
    }
}

// ---------------------------------------------------------------------------
// Kernels
// ---------------------------------------------------------------------------

// Q/K/V = x @ W^T ; blockIdx.z selects projection
__global__ __launch_bounds__(NTHREADS) void qkv_kernel(
    const float* __restrict__ x,
    const float* __restrict__ Wq,
    const float* __restrict__ Wk,
    const float* __restrict__ Wv)
{
    __shared__ __align__(16) float As[BK][BM];
    __shared__ __align__(16) float Bs[BK][BN];
    const float* W = (blockIdx.z == 0) ? Wq : (blockIdx.z == 1) ? Wk : Wv;
    float* out = (blockIdx.z == 0) ? g_Q : (blockIdx.z == 1) ? g_K : g_V;
    int m0 = blockIdx.y * BM, n0 = blockIdx.x * BN;
    float acc[TM][TN] = {};
    gemm_bt_acc(x, W, Cc, m0, n0, acc, As, Bs);
    store_tile(out, Cc, m0, n0, acc, nullptr);
}

// S = Q @ K^T * scale with causal mask; fully-masked tiles skip the GEMM.
__global__ __launch_bounds__(NTHREADS) void scores_kernel()
{
    const int b  = blockIdx.z;
    const int m0 = blockIdx.y * BM;
    const int n0 = blockIdx.x * BN;
    const int tx = threadIdx.x & 15;
    const int ty = threadIdx.x >> 4;
    float* S = g_S + (size_t)b * Tc * Tc;

    if (n0 > m0 + (BM - 1)) {   // tile entirely above diagonal
        const float4 v = make_float4(NEG_INF, NEG_INF, NEG_INF, NEG_INF);
        #pragma unroll
        for (int i = 0; i < TM; ++i) {
            int r = m0 + ty * TM + i;
            float* cp = S + (size_t)r * Tc + n0 + tx * TN;
            *(float4*)(cp) = v;
            *(float4*)(cp + 4) = v;
        }
        return;
    }

    __shared__ __align__(16) float As[BK][BM];
    __shared__ __align__(16) float Bs[BK][BN];
    float acc[TM][TN] = {};
    gemm_bt_acc(g_Q + (size_t)b * Tc * Cc, g_K + (size_t)b * Tc * Cc,
                Cc, m0, n0, acc, As, Bs);

    const float scale = 0.03125f;  // 1/sqrt(1024)
    #pragma unroll
    for (int i = 0; i < TM; ++i) {
        int r = m0 + ty * TM + i;
        float o[TN];
        #pragma unroll
        for (int j = 0; j < TN; ++j) {
            int c = n0 + tx * TN + j;
            o[j] = (c > r) ? NEG_INF : acc[i][j] * scale;
        }
        float* cp = S + (size_t)r * Tc + n0 + tx * TN;
        *(float4*)(cp)     = make_float4(o[0], o[1], o[2], o[3]);
        *(float4*)(cp + 4) = make_float4(o[4], o[5], o[6], o[7]);
    }
}

// Row softmax over T=4096, in place. One block per row; -inf entries -> 0.
__global__ __launch_bounds__(NTHREADS) void softmax_kernel()
{
    float* p = g_S + (size_t)blockIdx.x * Tc;
    const int tid = threadIdx.x;
    __shared__ float red[NTHREADS];

    float v[16];
    float m = NEG_INF;
    #pragma unroll
    for (int i = 0; i < 16; ++i) {
        v[i] = p[i * NTHREADS + tid];
        m = fmaxf(m, v[i]);
    }
    red[tid] = m;
    __syncthreads();
    for (int s = NTHREADS / 2; s > 0; s >>= 1) {
        if (tid < s) red[tid] = fmaxf(red[tid], red[tid + s]);
        __syncthreads();
    }
    m = red[0];
    __syncthreads();

    float sum = 0.0f;
    #pragma unroll
    for (int i = 0; i < 16; ++i) {
        v[i] = __expf(v[i] - m);
        sum += v[i];
    }
    red[tid] = sum;
    __syncthreads();
    for (int s = NTHREADS / 2; s > 0; s >>= 1) {
        if (tid < s) red[tid] += red[tid + s];
        __syncthreads();
    }
    const float inv = 1.0f / red[0];
    #pragma unroll
    for (int i = 0; i < 16; ++i) p[i * NTHREADS + tid] = v[i] * inv;
}

// O = P @ V ; K-loop bounded at m0+BM (P is zero beyond the causal diagonal).
__global__ __launch_bounds__(NTHREADS) void pv_kernel()
{
    const int b  = blockIdx.z;
    const int m0 = blockIdx.y * BM;
    const int n0 = blockIdx.x * BN;
    const float* P = g_S + (size_t)b * Tc * Tc;
    const float* V = g_V + (size_t)b * Tc * Cc;
    float* O = g_AO + (size_t)b * Tc * Cc;

    __shared__ __align__(16) float As[BK][BM];
    __shared__ __align__(16) float Bs[BK][BN];
    float acc[TM][TN] = {};
    gemm_nn_acc(P, V, Tc, Cc, m0, n0, m0 + BM, acc, As, Bs);
    store_tile(O, Cc, m0, n0, acc, nullptr);
}

// out = AO @ Wo^T + bo
__global__ __launch_bounds__(NTHREADS) void out_kernel(
    const float* __restrict__ Wo, const float* __restrict__ bo,
    float* __restrict__ out)
{
    int m0 = blockIdx.y * BM, n0 = blockIdx.x * BN;
    __shared__ __align__(16) float As[BK][BM];
    __shared__ __align__(16) float Bs[BK][BN];
    float acc[TM][TN] = {};
    gemm_bt_acc(g_AO, Wo, Cc, m0, n0, acc, As, Bs);
    store_tile(out, Cc, m0, n0, acc, bo);
}

// ---------------------------------------------------------------------------
extern "C" void kernel_launch(void* const* d_in, const int* in_sizes, int n_in,
                              void* d_out, int out_size)
{
    const float* x  = (const float*)d_in[0];
    const float* Wq = (const float*)d_in[1];
    const float* Wk = (const float*)d_in[2];
    const float* Wv = (const float*)d_in[3];
    const float* Wo = (const float*)d_in[4];
    const float* bo = (const float*)d_in[5];
    float* out = (float*)d_out;

    (void)in_sizes; (void)n_in; (void)out_size;

    qkv_kernel<<<dim3(Cc / BN, MT / BM, 3), NTHREADS>>>(x, Wq, Wk, Wv);
    scores_kernel<<<dim3(Tc / BN, Tc / BM, Bc), NTHREADS>>>();
    softmax_kernel<<<Bc * Tc, NTHREADS>>>();
    pv_kernel<<<dim3(Cc / BN, Tc / BM, Bc), NTHREADS>>>();
    out_kernel<<<dim3(Cc / BN, MT / BM), NTHREADS>>>(Wo, bo, out);
}

// round 3
// speedup vs baseline: 3.2675x; 3.2675x over previous
#include <cuda_runtime.h>
#include <cuda_bf16.h>
#include <cstdint>

#define T_ 4096
#define B_ 4
#define C_ 1024
#define MT_ (B_*T_)
#define STAGE_BYTES 65536
#define SMEM_DYN (2*STAGE_BYTES + 1024)

// ---------------- scratch (device globals; no cudaMalloc allowed) ----------
__device__ __align__(16) __nv_bfloat16 g_xhi[(size_t)MT_*C_];
__device__ __align__(16) __nv_bfloat16 g_xlo[(size_t)MT_*C_];
__device__ __align__(16) __nv_bfloat16 g_Whi[(size_t)4*C_*C_];
__device__ __align__(16) __nv_bfloat16 g_Wlo[(size_t)4*C_*C_];
__device__ __align__(16) __nv_bfloat16 g_Qhi[(size_t)MT_*C_];
__device__ __align__(16) __nv_bfloat16 g_Qlo[(size_t)MT_*C_];
__device__ __align__(16) __nv_bfloat16 g_Khi[(size_t)MT_*C_];
__device__ __align__(16) __nv_bfloat16 g_Klo[(size_t)MT_*C_];
__device__ __align__(16) __nv_bfloat16 g_Vthi[(size_t)MT_*C_];  // [B][C][T]
__device__ __align__(16) __nv_bfloat16 g_Vtlo[(size_t)MT_*C_];
__device__ __align__(16) float         g_S  [(size_t)B_*T_*T_];
__device__ __align__(16) __nv_bfloat16 g_Phi[(size_t)B_*T_*T_];
__device__ __align__(16) __nv_bfloat16 g_Plo[(size_t)B_*T_*T_];
__device__ __align__(16) __nv_bfloat16 g_AOhi[(size_t)MT_*C_];
__device__ __align__(16) __nv_bfloat16 g_AOlo[(size_t)MT_*C_];

extern __shared__ char dyn_smem[];

// ---------------- helpers ----------------------------------------------------
static __device__ __forceinline__ uint32_t smem_u32(const void* p){
  uint32_t a;
  asm("{ .reg .u64 t; cvta.to.shared.u64 t, %1; cvt.u32.u64 %0, t; }" : "=r"(a) : "l"(p));
  return a;
}
static __device__ __forceinline__ uint32_t swz(uint32_t o){ return o ^ ((o>>3)&0x70u); }

static __device__ __forceinline__ void ldsm4(uint32_t addr,
    uint32_t &r0, uint32_t &r1, uint32_t &r2, uint32_t &r3){
  asm volatile("ldmatrix.sync.aligned.m8n8.x4.shared.b16 {%0,%1,%2,%3}, [%4];"
    : "=r"(r0), "=r"(r1), "=r"(r2), "=r"(r3) : "r"(addr));
}
static __device__ __forceinline__ void mma16816(float* c,
    const uint32_t* a, const uint32_t* b){
  asm volatile("mma.sync.aligned.m16n8k16.row.col.f32.bf16.bf16.f32 "
    "{%0,%1,%2,%3}, {%4,%5,%6,%7}, {%8,%9}, {%0,%1,%2,%3};"
    : "+f"(c[0]), "+f"(c[1]), "+f"(c[2]), "+f"(c[3])
    : "r"(a[0]), "r"(a[1]), "r"(a[2]), "r"(a[3]), "r"(b[0]), "r"(b[1]));
}

// 128x64 bf16 tile (16KB) global -> SW128-swizzled smem via cp.async
static __device__ __forceinline__ void cp_tile(uint32_t sb,
    const __nv_bfloat16* __restrict__ g, int ldk){
  const int t = threadIdx.x;
#pragma unroll
  for (int i = 0; i < 4; ++i){
    int q = t + (i<<8);
    int row = q>>3, gr = q&7;
    const __nv_bfloat16* src = g + (size_t)row*ldk + (gr<<3);
    uint32_t dst = sb + swz((uint32_t)((row<<7)|(gr<<4)));
    asm volatile("cp.async.cg.shared.global [%0], [%1], 16;"
                 :: "r"(dst), "l"(src) : "memory");
  }
}
static __device__ __forceinline__ void cp_stage(uint32_t st,
    const __nv_bfloat16* Ahi, const __nv_bfloat16* Alo, int lda,
    const __nv_bfloat16* Bhi, const __nv_bfloat16* Blo, int ldb, int kt){
  cp_tile(st +     0, Ahi + kt, lda);
  cp_tile(st + 16384, Alo + kt, lda);
  cp_tile(st + 32768, Bhi + kt, ldb);
  cp_tile(st + 49152, Blo + kt, ldb);
}

// ---- core: acc[128,128] += (Ahi+Alo)[128,K] @ ((Bhi+Blo)[128,K])^T ---------
static __device__ __forceinline__ void hgemm_core(
    float (&acc)[4][4][4],
    const __nv_bfloat16* Ahi, const __nv_bfloat16* Alo, int lda,
    const __nv_bfloat16* Bhi, const __nv_bfloat16* Blo, int ldb, int K)
{
  const uint32_t sb = (smem_u32(dyn_smem) + 1023u) & ~1023u;
  const int tid = threadIdx.x, lane = tid&31, wid = tid>>5;
  const int wm = wid>>2, wn = wid&3;
  const int l7 = lane&7, sel = lane>>3;
  const int a_r = l7 + ((sel&1)<<3), a_g = sel>>1;   // A ldmatrix lane mapping
  const int b_r = l7 + ((sel>>1)<<3), b_g = sel&1;   // B ldmatrix lane mapping

  const int nc = K >> 6;
  cp_stage(sb, Ahi, Alo, lda, Bhi, Blo, ldb, 0);
  asm volatile("cp.async.commit_group;" ::: "memory");

  for (int c = 0; c < nc; ++c){
    const uint32_t st = sb + (uint32_t)(c&1)*STAGE_BYTES;
    if (c + 1 < nc){
      cp_stage(sb + (uint32_t)((c+1)&1)*STAGE_BYTES,
               Ahi, Alo, lda, Bhi, Blo, ldb, (c+1)<<6);
      asm volatile("cp.async.commit_group;" ::: "memory");
      asm volatile("cp.async.wait_group 1;" ::: "memory");
    } else {
      asm volatile("cp.async.wait_group 0;" ::: "memory");
    }
    __syncthreads();

#pragma unroll
    for (int ks = 0; ks < 4; ++ks){
      uint32_t ah[4][4], al[4][4], bh[4][2], bl[4][2];
#pragma unroll
      for (int mm = 0; mm < 4; ++mm){
        uint32_t ad = swz((uint32_t)(((wm*64 + mm*16 + a_r)<<7) | ((ks*2 + a_g)<<4)));
        ldsm4(st +         ad, ah[mm][0], ah[mm][1], ah[mm][2], ah[mm][3]);
        ldsm4(st + 16384 + ad, al[mm][0], al[mm][1], al[mm][2], al[mm][3]);
      }
#pragma unroll
      for (int nn2 = 0; nn2 < 2; ++nn2){
        uint32_t ad = swz((uint32_t)(((wn*32 + nn2*16 + b_r)<<7) | ((ks*2 + b_g)<<4)));
        uint32_t r0, r1, r2, r3;
        ldsm4(st + 32768 + ad, r0, r1, r2, r3);
        bh[nn2*2][0]=r0; bh[nn2*2][1]=r1; bh[nn2*2+1][0]=r2; bh[nn2*2+1][1]=r3;
        ldsm4(st + 49152 + ad, r0, r1, r2, r3);
        bl[nn2*2][0]=r0; bl[nn2*2][1]=r1; bl[nn2*2+1][0]=r2; bl[nn2*2+1][1]=r3;
      }
#pragma unroll
      for (int mm = 0; mm < 4; ++mm)
#pragma unroll
        for (int nn = 0; nn < 4; ++nn){
          mma16816(acc[mm][nn], ah[mm], bh[nn]);
          mma16816(acc[mm][nn], ah[mm], bl[nn]);
          mma16816(acc[mm][nn], al[mm], bh[nn]);
        }
    }
    if (c + 1 < nc) __syncthreads();
  }
}

static __device__ __forceinline__ void split_store2(
    __nv_bfloat16* H, __nv_bfloat16* L, size_t idx, float a, float b){
  __nv_bfloat16 ah = __float2bfloat16_rn(a), bh = __float2bfloat16_rn(b);
  __nv_bfloat16 alo = __float2bfloat16_rn(a - __bfloat162float(ah));
  __nv_bfloat16 blo = __float2bfloat16_rn(b - __bfloat162float(bh));
  *reinterpret_cast<__nv_bfloat162*>(H + idx) = __halves2bfloat162(ah, bh);
  *reinterpret_cast<__nv_bfloat162*>(L + idx) = __halves2bfloat162(alo, blo);
}
static __device__ __forceinline__ void split_store1(
    __nv_bfloat16* H, __nv_bfloat16* L, size_t idx, float a){
  __nv_bfloat16 ah = __float2bfloat16_rn(a);
  H[idx] = ah;
  L[idx] = __float2bfloat16_rn(a - __bfloat162float(ah));
}

// ---------------- fp32 -> split bf16 ---------------------------------------
__global__ __launch_bounds__(256) void split_k(
    const float* __restrict__ s, __nv_bfloat16* __restrict__ hi,
    __nv_bfloat16* __restrict__ lo)
{
  size_t i = ((size_t)blockIdx.x*256 + threadIdx.x)*4;
  float4 v = *reinterpret_cast<const float4*>(s + i);
  float f[4] = {v.x, v.y, v.z, v.w};
  __nv_bfloat16 h[4], l[4];
#pragma unroll
  for (int k = 0; k < 4; ++k){
    h[k] = __float2bfloat16_rn(f[k]);
    l[k] = __float2bfloat16_rn(f[k] - __bfloat162float(h[k]));
  }
  reinterpret_cast<__nv_bfloat162*>(hi + i)[0] = __halves2bfloat162(h[0], h[1]);
  reinterpret_cast<__nv_bfloat162*>(hi + i)[1] = __halves2bfloat162(h[2], h[3]);
  reinterpret_cast<__nv_bfloat162*>(lo + i)[0] = __halves2bfloat162(l[0], l[1]);
  reinterpret_cast<__nv_bfloat162*>(lo + i)[1] = __halves2bfloat162(l[2], l[3]);
}

// ---------------- GEMM kernels ----------------------------------------------
__global__ __launch_bounds__(256, 1) void qkv_tc()
{
  const int z = blockIdx.z, m0 = blockIdx.y<<7, n0 = blockIdx.x<<7;
  const size_t wo = (size_t)z*C_*C_;
  float acc[4][4][4] = {};
  hgemm_core(acc, g_xhi + (size_t)m0*C_, g_xlo + (size_t)m0*C_, C_,
             g_Whi + wo + (size_t)n0*C_, g_Wlo + wo + (size_t)n0*C_, C_, C_);

  const int lane = threadIdx.x&31, wid = threadIdx.x>>5;
  const int wm = wid>>2, wn = wid&3;
  const int rb = lane>>2, cb = (lane&3)*2;
#pragma unroll
  for (int mm = 0; mm < 4; ++mm)
#pragma unroll
    for (int nn = 0; nn < 4; ++nn){
      const int r  = m0 + wm*64 + mm*16 + rb;
      const int cc = n0 + wn*32 + nn*8 + cb;
      const float* a = acc[mm][nn];
      if (z == 2){                                   // V transposed: [b][c][t]
        const int b = r>>12, ml = r&(T_-1);
        size_t col0 = ((size_t)b*C_ + cc)*T_;
        split_store1(g_Vthi, g_Vtlo, col0 + ml,        a[0]);
        split_store1(g_Vthi, g_Vtlo, col0 + T_ + ml,   a[1]);
        split_store1(g_Vthi, g_Vtlo, col0 + ml + 8,    a[2]);
        split_store1(g_Vthi, g_Vtlo, col0 + T_ + ml+8, a[3]);
      } else {
        __nv_bfloat16* H = (z == 0) ? g_Qhi : g_Khi;
        __nv_bfloat16* L = (z == 0) ? g_Qlo : g_Klo;
        size_t base = (size_t)r*C_ + cc;
        split_store2(H, L, base,          a[0], a[1]);
        split_store2(H, L, base + 8*C_,   a[2], a[3]);
      }
    }
}

__global__ __launch_bounds__(256, 1) void scores_tc()
{
  if (blockIdx.x > blockIdx.y) return;               // fully-masked tile
  const int bz = blockIdx.z, m0 = blockIdx.y<<7, n0 = blockIdx.x<<7;
  const size_t qb = ((size_t)bz*T_ + m0)*C_;
  const size_t kb = ((size_t)bz*T_ + n0)*C_;
  float acc[4][4][4] = {};
  hgemm_core(acc, g_Qhi + qb, g_Qlo + qb, C_, g_Khi + kb, g_Klo + kb, C_, C_);

  const int lane = threadIdx.x&31, wid = threadIdx.x>>5;
  const int wm = wid>>2, wn = wid&3;
  const int rb = lane>>2, cb = (lane&3)*2;
#pragma unroll
  for (int mm = 0; mm < 4; ++mm)
#pragma unroll
    for (int nn = 0; nn < 4; ++nn){
      const int r  = m0 + wm*64 + mm*16 + rb;
      const int cc = n0 + wn*32 + nn*8 + cb;
      const float* a = acc[mm][nn];
      float* p = g_S + ((size_t)bz*T_ + r)*T_ + cc;
      *reinterpret_cast<float2*>(p)            = make_float2(a[0], a[1]);
      *reinterpret_cast<float2*>(p + 8ull*T_)  = make_float2(a[2], a[3]);
    }
}

__global__ __launch_bounds__(256, 1) void pv_tc()
{
  const int bz = blockIdx.z, m0 = blockIdx.y<<7, n0 = blockIdx.x<<7;
  const int K  = m0 + 128;
  const size_t pb = ((size_t)bz*T_ + m0)*T_;
  const size_t vb = ((size_t)bz*C_ + n0)*T_;
  float acc[4][4][4] = {};
  hgemm_core(acc, g_Phi + pb, g_Plo + pb, T_, g_Vthi + vb, g_Vtlo + vb, T_, K);

  const int lane = threadIdx.x&31, wid = threadIdx.x>>5;
  const int wm = wid>>2, wn = wid&3;
  const int rb = lane>>2, cb = (lane&3)*2;
#pragma unroll
  for (int mm = 0; mm < 4; ++mm)
#pragma unroll
    for (int nn = 0; nn < 4; ++nn){
      const int r  = m0 + wm*64 + mm*16 + rb;
      const int cc = n0 + wn*32 + nn*8 + cb;
      const float* a = acc[mm][nn];
      size_t base = ((size_t)bz*T_ + r)*C_ + cc;
      split_store2(g_AOhi, g_AOlo, base,        a[0], a[1]);
      split_store2(g_AOhi, g_AOlo, base + 8*C_, a[2], a[3]);
    }
}

__global__ __launch_bounds__(256, 1) void out_tc(const float* __restrict__ bo,
                                                 float* __restrict__ out)
{
  const int m0 = blockIdx.y<<7, n0 = blockIdx.x<<7;
  const size_t wo = (size_t)3*C_*C_;
  float acc[4][4][4] = {};
  hgemm_core(acc, g_AOhi + (size_t)m0*C_, g_AOlo + (size_t)m0*C_, C_,
             g_Whi + wo + (size_t)n0*C_, g_Wlo + wo + (size_t)n0*C_, C_, C_);

  const int lane = threadIdx.x&31, wid = threadIdx.x>>5;
  const int wm = wid>>2, wn = wid&3;
  const int rb = lane>>2, cb = (lane&3)*2;
#pragma unroll
  for (int mm = 0; mm < 4; ++mm)
#pragma unroll
    for (int nn = 0; nn < 4; ++nn){
      const int r  = m0 + wm*64 + mm*16 + rb;
      const int cc = n0 + wn*32 + nn*8 + cb;
      const float* a = acc[mm][nn];
      const float b0 = bo[cc], b1 = bo[cc+1];
      float* p = out + (size_t)r*C_ + cc;
      *reinterpret_cast<float2*>(p)          = make_float2(a[0]+b0, a[1]+b1);
      *reinterpret_cast<float2*>(p + 8*C_)   = make_float2(a[2]+b0, a[3]+b1);
    }
}

// ---------------- softmax: mask + scale + split-bf16 P ----------------------
__global__ __launch_bounds__(256) void softmax_k()
{
  const int gr = blockIdx.x;                 // 0..MT-1
  const int b  = gr >> 12, r = gr & (T_-1);
  const float* src = g_S + ((size_t)b*T_ + r)*T_;
  __nv_bfloat16* ph = g_Phi + ((size_t)b*T_ + r)*T_;
  __nv_bfloat16* pl = g_Plo + ((size_t)b*T_ + r)*T_;
  const int tid = threadIdx.x;
  const int nv  = r + 1;
  const int kmax = ((r >> 7) + 1) << 7;      // pad to 128 (GEMM chunk granularity... covered by 64)
  const float scale = 0.03125f;              // 1/sqrt(1024)
  __shared__ float red[256];

  float m = __int_as_float(0xff800000);
  for (int c = tid; c < nv; c += 256) m = fmaxf(m, src[c]);
  red[tid] = m; __syncthreads();
  for (int s = 128; s > 0; s >>= 1){
    if (tid < s) red[tid] = fmaxf(red[tid], red[tid + s]);
    __syncthreads();
  }
  m = red[0]; __syncthreads();

  float sum = 0.f;
  for (int c = tid; c < nv; c += 256) sum += __expf((src[c] - m) * scale);
  red[tid] = sum; __syncthreads();
  for (int s = 128; s > 0; s >>= 1){
    if (tid < s) red[tid] += red[tid + s];
    __syncthreads();
  }
  const float inv = 1.f / red[0];

  for (int c = tid; c < kmax; c += 256){
    float p = (c < nv) ? __expf((src[c] - m) * scale) * inv : 0.f;
    __nv_bfloat16 h = __float2bfloat16_rn(p);
    ph[c] = h;
    pl[c] = __float2bfloat16_rn(p - __bfloat162float(h));
  }
}

// ---------------- launch -----------------------------------------------------
extern "C" void kernel_launch(void* const* d_in, const int* in_sizes, int n_in,
                              void* d_out, int out_size)
{
  const float* x  = (const float*)d_in[0];
  const float* Wq = (const float*)d_in[1];
  const float* Wk = (const float*)d_in[2];
  const float* Wv = (const float*)d_in[3];
  const float* Wo = (const float*)d_in[4];
  const float* bo = (const float*)d_in[5];
  float* out = (float*)d_out;
  (void)in_sizes; (void)n_in; (void)out_size;

  cudaFuncSetAttribute(qkv_tc,    cudaFuncAttributeMaxDynamicSharedMemorySize, SMEM_DYN);
  cudaFuncSetAttribute(scores_tc, cudaFuncAttributeMaxDynamicSharedMemorySize, SMEM_DYN);
  cudaFuncSetAttribute(pv_tc,     cudaFuncAttributeMaxDynamicSharedMemorySize, SMEM_DYN);
  cudaFuncSetAttribute(out_tc,    cudaFuncAttributeMaxDynamicSharedMemorySize, SMEM_DYN);

  __nv_bfloat16 *whi, *wlo, *xhi, *xlo;
  cudaGetSymbolAddress((void**)&whi, g_Whi);
  cudaGetSymbolAddress((void**)&wlo, g_Wlo);
  cudaGetSymbolAddress((void**)&xhi, g_xhi);
  cudaGetSymbolAddress((void**)&xlo, g_xlo);

  split_k<<<(size_t)MT_*C_/1024, 256>>>(x, xhi, xlo);
  split_k<<<(size_t)C_*C_/1024, 256>>>(Wq, whi + 0*(size_t)C_*C_, wlo + 0*(size_t)C_*C_);
  split_k<<<(size_t)C_*C_/1024, 256>>>(Wk, whi + 1*(size_t)C_*C_, wlo + 1*(size_t)C_*C_);
  split_k<<<(size_t)C_*C_/1024, 256>>>(Wv, whi + 2*(size_t)C_*C_, wlo + 2*(size_t)C_*C_);
  split_k<<<(size_t)C_*C_/1024, 256>>>(Wo, whi + 3*(size_t)C_*C_, wlo + 3*(size_t)C_*C_);

  qkv_tc   <<<dim3(C_/128, MT_/128, 3), 256, SMEM_DYN>>>();
  scores_tc<<<dim3(T_/128, T_/128, B_), 256, SMEM_DYN>>>();
  softmax_k<<<MT_, 256>>>();
  pv_tc    <<<dim3(C_/128, T_/128, B_), 256, SMEM_DYN>>>();
  out_tc   <<<dim3(C_/128, MT_/128, 1), 256, SMEM_DYN>>>(bo, out);
}